// round 7
// baseline (speedup 1.0000x reference)
#include <cuda_runtime.h>

// z_hat [B,T,D] f32, P [B,T] f32, lengths [B] i32 -> out [B,T,D] f32
#define BB 4
#define TT 4096
#define DD 512
#define CC 256              // chunks along T
#define LL 16               // chunk length
#define D4 128              // float4 lanes per row (DD/4)
#define NCHUNK (BB*CC)      // 1024 flattened chunks, f = c*BB + b
#define NBLOCKS 512         // one co-resident wave (<= 148*4)
#define THREADS 128

// Scratch (__device__ globals; allocation-free rule). Indexed by f = c*BB + b.
__device__ float g_Bsum[NCHUNK * DD];
__device__ float g_A[NCHUNK];
__device__ float g_Zinit[NCHUNK * DD];
__device__ unsigned g_bar;   // monotonic; each launch adds exactly 2*NBLOCKS
                             // (multiple of NBLOCKS, wrap-safe) -> deterministic

// Grid-wide barrier: all NBLOCKS blocks are co-resident (launch_bounds
// guarantees >=4 blocks/SM; 148*4=592 >= 512), so spinning is deadlock-free.
__device__ __forceinline__ void grid_barrier()
{
    __syncthreads();
    __threadfence();
    if (threadIdx.x == 0) {
        unsigned my = atomicAdd(&g_bar, 1u) + 1u;
        unsigned target = ((my + NBLOCKS - 1u) / NBLOCKS) * NBLOCKS;
        volatile unsigned* p = &g_bar;
        while ((int)(*p - target) < 0) { }
        __threadfence();
    }
    __syncthreads();
}

__device__ __forceinline__ void load_pq(const float* __restrict__ P,
                                        int b, int t0, float* pv, float* qv)
{
#pragma unroll
    for (int k = 0; k < LL; ++k) {
        float p = __ldg(&P[b * TT + t0 + k]);     // warp-uniform broadcast
        p = fminf(fmaxf(p, 0.0f), 1.0f - 1e-6f);
        qv[k] = 1.0f - p;
        pv[k] = fmaxf(p, 1e-6f);
    }
}

__global__ void __launch_bounds__(THREADS, 4) fused_smoothing(
    const float* __restrict__ z, const float* __restrict__ P,
    const int* __restrict__ lengths, float* __restrict__ out)
{
    const int j = blockIdx.x;       // 0..NBLOCKS-1
    const int lane = threadIdx.x;   // float4 lane over D

    // ---------------- Phase 1: per-chunk summaries ----------------
    // Block j owns flattened chunks f = j and f = j + NBLOCKS (f = c*BB + b).
#pragma unroll
    for (int half = 0; half < 2; ++half) {
        const int f = j + half * NBLOCKS;
        const int b = f & (BB - 1);
        const int c = f >> 2;
        const int len = lengths[b];
        const int t0 = c * LL;
        if (t0 >= len) continue;     // masked chunk: state never consumed

        float pv[LL], qv[LL];
        load_pq(P, b, t0, pv, qv);
        float w[LL];
        float r = 1.0f;
#pragma unroll
        for (int k = LL - 1; k >= 0; --k) { w[k] = pv[k] * r; r *= qv[k]; }

        const float4* __restrict__ zp =
            (const float4*)(z + ((size_t)b * TT + t0) * DD);
        float4 acc = make_float4(0.f, 0.f, 0.f, 0.f);
#pragma unroll
        for (int kb = 0; kb < LL; kb += 8) {
            float4 x0 = zp[(size_t)(kb + 0) * D4 + lane];
            float4 x1 = zp[(size_t)(kb + 1) * D4 + lane];
            float4 x2 = zp[(size_t)(kb + 2) * D4 + lane];
            float4 x3 = zp[(size_t)(kb + 3) * D4 + lane];
            float4 x4 = zp[(size_t)(kb + 4) * D4 + lane];
            float4 x5 = zp[(size_t)(kb + 5) * D4 + lane];
            float4 x6 = zp[(size_t)(kb + 6) * D4 + lane];
            float4 x7 = zp[(size_t)(kb + 7) * D4 + lane];
            acc.x = fmaf(w[kb+0], x0.x, acc.x); acc.y = fmaf(w[kb+0], x0.y, acc.y);
            acc.z = fmaf(w[kb+0], x0.z, acc.z); acc.w = fmaf(w[kb+0], x0.w, acc.w);
            acc.x = fmaf(w[kb+1], x1.x, acc.x); acc.y = fmaf(w[kb+1], x1.y, acc.y);
            acc.z = fmaf(w[kb+1], x1.z, acc.z); acc.w = fmaf(w[kb+1], x1.w, acc.w);
            acc.x = fmaf(w[kb+2], x2.x, acc.x); acc.y = fmaf(w[kb+2], x2.y, acc.y);
            acc.z = fmaf(w[kb+2], x2.z, acc.z); acc.w = fmaf(w[kb+2], x2.w, acc.w);
            acc.x = fmaf(w[kb+3], x3.x, acc.x); acc.y = fmaf(w[kb+3], x3.y, acc.y);
            acc.z = fmaf(w[kb+3], x3.z, acc.z); acc.w = fmaf(w[kb+3], x3.w, acc.w);
            acc.x = fmaf(w[kb+4], x4.x, acc.x); acc.y = fmaf(w[kb+4], x4.y, acc.y);
            acc.z = fmaf(w[kb+4], x4.z, acc.z); acc.w = fmaf(w[kb+4], x4.w, acc.w);
            acc.x = fmaf(w[kb+5], x5.x, acc.x); acc.y = fmaf(w[kb+5], x5.y, acc.y);
            acc.z = fmaf(w[kb+5], x5.z, acc.z); acc.w = fmaf(w[kb+5], x5.w, acc.w);
            acc.x = fmaf(w[kb+6], x6.x, acc.x); acc.y = fmaf(w[kb+6], x6.y, acc.y);
            acc.z = fmaf(w[kb+6], x6.z, acc.z); acc.w = fmaf(w[kb+6], x6.w, acc.w);
            acc.x = fmaf(w[kb+7], x7.x, acc.x); acc.y = fmaf(w[kb+7], x7.y, acc.y);
            acc.z = fmaf(w[kb+7], x7.z, acc.z); acc.w = fmaf(w[kb+7], x7.w, acc.w);
        }
        ((float4*)g_Bsum)[(size_t)f * D4 + lane] = acc;
        if (lane == 0) g_A[f] = r;
    }

    grid_barrier();

    // ---------------- Phase 2: cross-chunk parallel scan ----------------
    // Block j handles scan instance (b = j&3, g = j>>2): Hillis-Steele over
    // the CC=256 affine maps, pair-combined to 128 (7 smem steps).
    // CONSISTENT flattening: chunk (b,c) lives at f = c*BB + b.
    {
        const int b = j & (BB - 1);
        const int g = j >> 2;
        const int i = lane;                  // 0..127 -> chunk pair (2i, 2i+1)
        const int f0 = (2 * i) * BB + b;
        const int f1 = (2 * i + 1) * BB + b;

        float a0 = g_A[f0];
        float a1 = g_A[f1];
        float4 v0 = ((const float4*)g_Bsum)[(size_t)f0 * D4 + g];
        float4 v1 = ((const float4*)g_Bsum)[(size_t)f1 * D4 + g];

        // combined pair map (apply chunk 2i then 2i+1)
        float  ac = a1 * a0;
        float4 bc = make_float4(fmaf(a1, v0.x, v1.x), fmaf(a1, v0.y, v1.y),
                                fmaf(a1, v0.z, v1.z), fmaf(a1, v0.w, v1.w));

        __shared__ float sA[128];
        __shared__ float4 sB[128];
        sA[i] = ac; sB[i] = bc;
        __syncthreads();
#pragma unroll
        for (int s = 1; s < 128; s <<= 1) {
            float pa = 1.0f;
            float4 pb = make_float4(0.f, 0.f, 0.f, 0.f);
            if (i >= s) { pa = sA[i - s]; pb = sB[i - s]; }
            __syncthreads();
            if (i >= s) {
                bc.x = fmaf(ac, pb.x, bc.x);
                bc.y = fmaf(ac, pb.y, bc.y);
                bc.z = fmaf(ac, pb.z, bc.z);
                bc.w = fmaf(ac, pb.w, bc.w);
                ac *= pa;
                sA[i] = ac; sB[i] = bc;
            }
            __syncthreads();
        }
        // exclusive prefix entering pair i
        float4 Eb = (i == 0) ? make_float4(0.f, 0.f, 0.f, 0.f) : sB[i - 1];
        float4* __restrict__ zi = (float4*)g_Zinit;
        zi[(size_t)f0 * D4 + g] = Eb;
        zi[(size_t)f1 * D4 + g] =
            make_float4(fmaf(a0, Eb.x, v0.x), fmaf(a0, Eb.y, v0.y),
                        fmaf(a0, Eb.z, v0.z), fmaf(a0, Eb.w, v0.w));
    }

    grid_barrier();

    // ---------------- Phase 3: local scan + masked output ----------------
    // Same chunks as phase 1 -> z re-reads hit this SM's L1/L2.
#pragma unroll
    for (int half = 0; half < 2; ++half) {
        const int f = j + half * NBLOCKS;
        const int b = f & (BB - 1);
        const int c = f >> 2;
        const int len = lengths[b];
        const int t0 = c * LL;

        float4* __restrict__ op = (float4*)(out + ((size_t)b * TT + t0) * DD);

        if (t0 >= len) {                    // fully masked: zero-fill, no loads
            float4 zero = make_float4(0.f, 0.f, 0.f, 0.f);
#pragma unroll
            for (int k = 0; k < LL; ++k) op[(size_t)k * D4 + lane] = zero;
            continue;
        }

        float4 zv = ((const float4*)g_Zinit)[(size_t)f * D4 + lane];

        float pv[LL], qv[LL];
        load_pq(P, b, t0, pv, qv);

        const float4* __restrict__ zp =
            (const float4*)(z + ((size_t)b * TT + t0) * DD);
#pragma unroll
        for (int kb = 0; kb < LL; kb += 8) {
            float4 x0 = zp[(size_t)(kb + 0) * D4 + lane];
            float4 x1 = zp[(size_t)(kb + 1) * D4 + lane];
            float4 x2 = zp[(size_t)(kb + 2) * D4 + lane];
            float4 x3 = zp[(size_t)(kb + 3) * D4 + lane];
            float4 x4 = zp[(size_t)(kb + 4) * D4 + lane];
            float4 x5 = zp[(size_t)(kb + 5) * D4 + lane];
            float4 x6 = zp[(size_t)(kb + 6) * D4 + lane];
            float4 x7 = zp[(size_t)(kb + 7) * D4 + lane];
#pragma unroll
            for (int u = 0; u < 8; ++u) {
                const int kk = kb + u;
                float4 x = (u == 0) ? x0 : (u == 1) ? x1 : (u == 2) ? x2 : (u == 3) ? x3
                         : (u == 4) ? x4 : (u == 5) ? x5 : (u == 6) ? x6 : x7;
                float q = qv[kk], p = pv[kk];
                zv.x = fmaf(q, zv.x, p * x.x);
                zv.y = fmaf(q, zv.y, p * x.y);
                zv.z = fmaf(q, zv.z, p * x.z);
                zv.w = fmaf(q, zv.w, p * x.w);
                float m = (t0 + kk < len) ? 1.0f : 0.0f;
                op[(size_t)kk * D4 + lane] =
                    make_float4(zv.x * m, zv.y * m, zv.z * m, zv.w * m);
            }
        }
    }
}

extern "C" void kernel_launch(void* const* d_in, const int* in_sizes, int n_in,
                              void* d_out, int out_size)
{
    const float* z = (const float*)d_in[0];
    const float* P = (const float*)d_in[1];
    const int* lengths = (const int*)d_in[2];
    float* out = (float*)d_out;

    fused_smoothing<<<NBLOCKS, THREADS>>>(z, P, lengths, out);
}